// round 1
// baseline (speedup 1.0000x reference)
#include <cuda_runtime.h>

// Problem constants (B, C, H, W, N) = (4, 5, 256, 256, 2048)
#define BB      4
#define CC      5
#define HGT     256
#define WID     256
#define HW      65536
#define NQ      2048
#define QT      8                    // queries per CTA
#define QTILES  (NQ / QT)            // 256 (worst case all queries in one batch)
#define STILES  4                    // HW splits
#define SPER    (HW / STILES)        // 16384
#define THREADS 256
#define ITERS2  (SPER / (2 * THREADS))  // 32 float2 iters per thread

// Scratch (static device globals; no allocation allowed)
__device__ float    g_K[BB * CC * HW];
__device__ float    g_V[BB * CC * HW];
__device__ float    g_qs[NQ * CC];       // q_pix * log2(e)
__device__ float    g_mb[NQ];            // upper bound on energy, * log2(e)
__device__ int      g_count[BB];
__device__ int      g_perm[BB * NQ];
__device__ unsigned g_amax[BB * CC];     // max |K| per (b,c), as float bits
__device__ float    g_part[NQ * STILES * 6];  // per (query, s-tile): [l, acc0..acc4]

// ---------------------------------------------------------------------------
__global__ void init_kernel() {
    int t = threadIdx.x;
    if (t < BB) g_count[t] = 0;
    if (t < BB * CC) g_amax[t] = 0u;
}

// ---------------------------------------------------------------------------
// K,V 1x1 conv + y = x copy + per-(b,c) max|K| reduction
__global__ void kv_kernel(const float* __restrict__ x,
                          const float* __restrict__ Wk, const float* __restrict__ bk,
                          const float* __restrict__ Wv, const float* __restrict__ bv,
                          float* __restrict__ y) {
    __shared__ float sWk[CC * CC], sWv[CC * CC], sbk[CC], sbv[CC];
    __shared__ unsigned samax[CC];
    int t = threadIdx.x;
    if (t < CC * CC) { sWk[t] = Wk[t]; sWv[t] = Wv[t]; }
    if (t < CC)      { sbk[t] = bk[t]; sbv[t] = bv[t]; samax[t] = 0u; }
    __syncthreads();

    int idx = blockIdx.x * THREADS + t;   // 0 .. B*HW-1; b uniform per block
    int b = idx >> 16;
    int s = idx & (HW - 1);

    float xv[CC];
#pragma unroll
    for (int c = 0; c < CC; c++) {
        xv[c] = x[(b * CC + c) * HW + s];
        y[(b * CC + c) * HW + s] = xv[c];   // residual base copy
    }

    float ka[CC];
#pragma unroll
    for (int o = 0; o < CC; o++) {
        float kk = sbk[o], vv = sbv[o];
#pragma unroll
        for (int c = 0; c < CC; c++) {
            kk = fmaf(sWk[o * CC + c], xv[c], kk);
            vv = fmaf(sWv[o * CC + c], xv[c], vv);
        }
        g_K[(b * CC + o) * HW + s] = kk;
        g_V[(b * CC + o) * HW + s] = vv;
        ka[o] = fabsf(kk);
    }

    int lane = t & 31;
#pragma unroll
    for (int o = 0; o < CC; o++) {
        float m = ka[o];
#pragma unroll
        for (int off = 16; off > 0; off >>= 1)
            m = fmaxf(m, __shfl_xor_sync(0xffffffffu, m, off));
        if (lane == 0) atomicMax(&samax[o], __float_as_uint(m));
    }
    __syncthreads();
    if (t < CC) atomicMax(&g_amax[b * CC + t], samax[t]);
}

// ---------------------------------------------------------------------------
// q_pix, energy upper bound, batch bucketing
__global__ void qprep_kernel(const float* __restrict__ x,
                             const float* __restrict__ Wq, const float* __restrict__ bq,
                             const int* __restrict__ idx_b, const int* __restrict__ idx_h,
                             const int* __restrict__ idx_w) {
    __shared__ float sWq[CC * CC], sbq[CC];
    int t = threadIdx.x;
    if (t < CC * CC) sWq[t] = Wq[t];
    if (t < CC)      sbq[t] = bq[t];
    __syncthreads();

    int n = blockIdx.x * THREADS + t;
    if (n >= NQ) return;

    int b = idx_b[n];
    int s = idx_h[n] * WID + idx_w[n];

    float xv[CC];
#pragma unroll
    for (int c = 0; c < CC; c++) xv[c] = x[(b * CC + c) * HW + s];

    const float L2E = 1.4426950408889634f;
    float m = 0.0f;
#pragma unroll
    for (int o = 0; o < CC; o++) {
        float q = sbq[o];
#pragma unroll
        for (int c = 0; c < CC; c++) q = fmaf(sWq[o * CC + c], xv[c], q);
        g_qs[n * CC + o] = q * L2E;
        m = fmaf(fabsf(q), __uint_as_float(g_amax[b * CC + o]), m);
    }
    g_mb[n] = m * L2E;   // guarantees e*L2E - mb <= 0 for every s

    int pos = atomicAdd(&g_count[b], 1);
    g_perm[b * NQ + pos] = n;
}

// ---------------------------------------------------------------------------
// Main attention kernel: 8 queries x 16384 s-positions per CTA, branchless
// exp2-poly softmax with static max bound, deterministic tree reduction.
__global__ void __launch_bounds__(THREADS)
attn_kernel() {
    int b   = blockIdx.y;
    int cnt = g_count[b];
    int q0  = blockIdx.x * QT;
    if (q0 >= cnt) return;
    int st  = blockIdx.z;
    int t   = threadIdx.x;
    int nq  = min(QT, cnt - q0);

    float qs[QT][CC], nmb[QT];
#pragma unroll
    for (int j = 0; j < QT; j++) {
        int slot = (j < nq) ? (q0 + j) : q0;          // pad with query 0 (not stored)
        int n = g_perm[b * NQ + slot];
#pragma unroll
        for (int c = 0; c < CC; c++) qs[j][c] = g_qs[n * CC + c];
        nmb[j] = -g_mb[n];
    }

    const float2* __restrict__ K2 = (const float2*)(g_K + b * CC * HW);
    const float2* __restrict__ V2 = (const float2*)(g_V + b * CC * HW);

    float l[QT];
    float ac[QT][CC];
#pragma unroll
    for (int j = 0; j < QT; j++) {
        l[j] = 0.0f;
#pragma unroll
        for (int c = 0; c < CC; c++) ac[j][c] = 0.0f;
    }

    const float MAGIC = 12582912.0f;   // 1.5 * 2^23
    int sp = st * (SPER / 2) + t;

#pragma unroll 1
    for (int it = 0; it < ITERS2; it++, sp += THREADS) {
        float2 k0 = K2[sp];
        float2 k1 = K2[(HW / 2) + sp];
        float2 k2 = K2[2 * (HW / 2) + sp];
        float2 k3 = K2[3 * (HW / 2) + sp];
        float2 k4 = K2[4 * (HW / 2) + sp];
        float2 v0 = V2[sp];
        float2 v1 = V2[(HW / 2) + sp];
        float2 v2 = V2[2 * (HW / 2) + sp];
        float2 v3 = V2[3 * (HW / 2) + sp];
        float2 v4 = V2[4 * (HW / 2) + sp];

#pragma unroll
        for (int j = 0; j < QT; j++) {
#pragma unroll
            for (int e = 0; e < 2; e++) {
                float kk0 = e ? k0.y : k0.x, kk1 = e ? k1.y : k1.x;
                float kk2 = e ? k2.y : k2.x, kk3 = e ? k3.y : k3.x;
                float kk4 = e ? k4.y : k4.x;
                float vv0 = e ? v0.y : v0.x, vv1 = e ? v1.y : v1.x;
                float vv2 = e ? v2.y : v2.x, vv3 = e ? v3.y : v3.x;
                float vv4 = e ? v4.y : v4.x;

                // scaled energy (already in log2 domain), t <= 0
                float tt = nmb[j];
                tt = fmaf(qs[j][0], kk0, tt);
                tt = fmaf(qs[j][1], kk1, tt);
                tt = fmaf(qs[j][2], kk2, tt);
                tt = fmaf(qs[j][3], kk3, tt);
                tt = fmaf(qs[j][4], kk4, tt);
                tt = fmaxf(tt, -110.0f);

                // exp2 via round-to-int magic + deg-4 poly + exponent bit add
                float r = tt + MAGIC;
                float f = tt - (r - MAGIC);          // f in [-0.5, 0.5]
                float p = fmaf(0.0096181291f, f, 0.0555041087f);
                p = fmaf(p, f, 0.2402265070f);
                p = fmaf(p, f, 0.6931471806f);
                p = fmaf(p, f, 1.0f);
                p = __int_as_float(__float_as_int(p) + (__float_as_int(r) << 23));

                l[j] += p;
                ac[j][0] = fmaf(p, vv0, ac[j][0]);
                ac[j][1] = fmaf(p, vv1, ac[j][1]);
                ac[j][2] = fmaf(p, vv2, ac[j][2]);
                ac[j][3] = fmaf(p, vv3, ac[j][3]);
                ac[j][4] = fmaf(p, vv4, ac[j][4]);
            }
        }
    }

    // Deterministic reduction: warp butterfly -> smem -> fixed-order sum
    __shared__ float red[8][QT][6];
    int warp = t >> 5, lane = t & 31;
#pragma unroll
    for (int j = 0; j < QT; j++) {
        float vals[6];
        vals[0] = l[j];
#pragma unroll
        for (int c = 0; c < CC; c++) vals[1 + c] = ac[j][c];
#pragma unroll
        for (int k = 0; k < 6; k++) {
            float v = vals[k];
#pragma unroll
            for (int off = 16; off > 0; off >>= 1)
                v += __shfl_xor_sync(0xffffffffu, v, off);
            if (lane == 0) red[warp][j][k] = v;
        }
    }
    __syncthreads();

    if (t < QT * 6) {
        int j = t / 6, k = t % 6;
        if (j < nq) {
            float ssum = 0.0f;
#pragma unroll
            for (int w2 = 0; w2 < 8; w2++) ssum += red[w2][j][k];
            int n = g_perm[b * NQ + q0 + j];
            g_part[(n * STILES + st) * 6 + k] = ssum;
        }
    }
}

// ---------------------------------------------------------------------------
__global__ void finalize_kernel(const float* __restrict__ x,
                                const float* __restrict__ gamma,
                                const int* __restrict__ idx_b, const int* __restrict__ idx_h,
                                const int* __restrict__ idx_w,
                                float* __restrict__ y) {
    int n = blockIdx.x * THREADS + threadIdx.x;
    if (n >= NQ) return;

    float l = 0.0f, a[CC] = {0.f, 0.f, 0.f, 0.f, 0.f};
#pragma unroll
    for (int st = 0; st < STILES; st++) {
        const float* p = g_part + (n * STILES + st) * 6;
        l += p[0];
#pragma unroll
        for (int c = 0; c < CC; c++) a[c] += p[1 + c];
    }

    float g = gamma[0] + 0.1f;
    float inv = 1.0f / l;
    int b = idx_b[n];
    int s = idx_h[n] * WID + idx_w[n];
#pragma unroll
    for (int c = 0; c < CC; c++) {
        float out = a[c] * inv;
        y[(b * CC + c) * HW + s] = fmaf(g, out, x[(b * CC + c) * HW + s]);
    }
}

// ---------------------------------------------------------------------------
extern "C" void kernel_launch(void* const* d_in, const int* in_sizes, int n_in,
                              void* d_out, int out_size) {
    const float* x     = (const float*)d_in[0];
    const float* Wq    = (const float*)d_in[1];
    const float* bq    = (const float*)d_in[2];
    const float* Wk    = (const float*)d_in[3];
    const float* bk    = (const float*)d_in[4];
    const float* Wv    = (const float*)d_in[5];
    const float* bv    = (const float*)d_in[6];
    const float* gamma = (const float*)d_in[7];
    const int* idx_b   = (const int*)d_in[8];
    const int* idx_h   = (const int*)d_in[9];
    const int* idx_w   = (const int*)d_in[10];
    float* y = (float*)d_out;

    init_kernel<<<1, 32>>>();
    kv_kernel<<<(BB * HW) / THREADS, THREADS>>>(x, Wk, bk, Wv, bv, y);
    qprep_kernel<<<NQ / THREADS, THREADS>>>(x, Wq, bq, idx_b, idx_h, idx_w);
    attn_kernel<<<dim3(QTILES, BB, STILES), THREADS>>>();
    finalize_kernel<<<NQ / THREADS, THREADS>>>(x, gamma, idx_b, idx_h, idx_w, y);
}

// round 3
// speedup vs baseline: 1.0854x; 1.0854x over previous
#include <cuda_runtime.h>

// Problem constants (B, C, H, W, N) = (4, 5, 256, 256, 2048)
#define BB      4
#define CC      5
#define HGT     256
#define WID     256
#define HW      65536
#define NQ      2048
#define QT      8                    // queries per CTA
#define QTILES  (NQ / QT)            // 256 (worst case all queries in one batch)
#define STILES  4                    // HW splits
#define SPER    (HW / STILES)        // 16384
#define THREADS 256
#define ITERS2  (SPER / (2 * THREADS))  // 32 float2 iters per thread

typedef unsigned long long u64;

// Scratch (static device globals; no allocation allowed)
__device__ float    g_K[BB * CC * HW];
__device__ float    g_V[BB * CC * HW];
__device__ float    g_qs[NQ * CC];       // q_pix * log2(e)
__device__ int      g_bias[NQ];          // -(0x4B400000 + ceil(mb*log2e))
__device__ int      g_count[BB];
__device__ int      g_perm[BB * NQ];
__device__ unsigned g_amax[BB * CC];     // max |K| per (b,c), as float bits
__device__ float    g_part[NQ * STILES * 6];  // per (query, s-tile): [l, acc0..acc4]

// ---------------- packed f32x2 helpers (sm_103a) ---------------------------
__device__ __forceinline__ u64 pk2(float x, float y) {
    u64 r; asm("mov.b64 %0, {%1, %2};" : "=l"(r) : "f"(x), "f"(y)); return r;
}
__device__ __forceinline__ u64 pk2u(unsigned lo, unsigned hi) {
    u64 r; asm("mov.b64 %0, {%1, %2};" : "=l"(r) : "r"(lo), "r"(hi)); return r;
}
__device__ __forceinline__ void unpk2u(u64 v, unsigned& lo, unsigned& hi) {
    asm("mov.b64 {%0, %1}, %2;" : "=r"(lo), "=r"(hi) : "l"(v));
}
__device__ __forceinline__ void unpk2f(u64 v, float& lo, float& hi) {
    asm("mov.b64 {%0, %1}, %2;" : "=f"(lo), "=f"(hi) : "l"(v));
}
__device__ __forceinline__ u64 fma2(u64 a, u64 b, u64 c) {
    u64 d; asm("fma.rn.f32x2 %0, %1, %2, %3;" : "=l"(d) : "l"(a), "l"(b), "l"(c)); return d;
}
__device__ __forceinline__ u64 mul2(u64 a, u64 b) {
    u64 d; asm("mul.rn.f32x2 %0, %1, %2;" : "=l"(d) : "l"(a), "l"(b)); return d;
}
__device__ __forceinline__ u64 add2(u64 a, u64 b) {
    u64 d; asm("add.rn.f32x2 %0, %1, %2;" : "=l"(d) : "l"(a), "l"(b)); return d;
}

// ---------------------------------------------------------------------------
__global__ void init_kernel() {
    int t = threadIdx.x;
    if (t < BB) g_count[t] = 0;
    if (t < BB * CC) g_amax[t] = 0u;
}

// ---------------------------------------------------------------------------
// K,V 1x1 conv + y = x copy + per-(b,c) max|K| reduction
__global__ void kv_kernel(const float* __restrict__ x,
                          const float* __restrict__ Wk, const float* __restrict__ bk,
                          const float* __restrict__ Wv, const float* __restrict__ bv,
                          float* __restrict__ y) {
    __shared__ float sWk[CC * CC], sWv[CC * CC], sbk[CC], sbv[CC];
    __shared__ unsigned samax[CC];
    int t = threadIdx.x;
    if (t < CC * CC) { sWk[t] = Wk[t]; sWv[t] = Wv[t]; }
    if (t < CC)      { sbk[t] = bk[t]; sbv[t] = bv[t]; samax[t] = 0u; }
    __syncthreads();

    int idx = blockIdx.x * THREADS + t;   // 0 .. B*HW-1; b uniform per block
    int b = idx >> 16;
    int s = idx & (HW - 1);

    float xv[CC];
#pragma unroll
    for (int c = 0; c < CC; c++) {
        xv[c] = x[(b * CC + c) * HW + s];
        y[(b * CC + c) * HW + s] = xv[c];   // residual base copy
    }

    float ka[CC];
#pragma unroll
    for (int o = 0; o < CC; o++) {
        float kk = sbk[o], vv = sbv[o];
#pragma unroll
        for (int c = 0; c < CC; c++) {
            kk = fmaf(sWk[o * CC + c], xv[c], kk);
            vv = fmaf(sWv[o * CC + c], xv[c], vv);
        }
        g_K[(b * CC + o) * HW + s] = kk;
        g_V[(b * CC + o) * HW + s] = vv;
        ka[o] = fabsf(kk);
    }

    int lane = t & 31;
#pragma unroll
    for (int o = 0; o < CC; o++) {
        float m = ka[o];
#pragma unroll
        for (int off = 16; off > 0; off >>= 1)
            m = fmaxf(m, __shfl_xor_sync(0xffffffffu, m, off));
        if (lane == 0) atomicMax(&samax[o], __float_as_uint(m));
    }
    __syncthreads();
    if (t < CC) atomicMax(&g_amax[b * CC + t], samax[t]);
}

// ---------------------------------------------------------------------------
// q_pix, integer exponent bias, batch bucketing
__global__ void qprep_kernel(const float* __restrict__ x,
                             const float* __restrict__ Wq, const float* __restrict__ bq,
                             const int* __restrict__ idx_b, const int* __restrict__ idx_h,
                             const int* __restrict__ idx_w) {
    __shared__ float sWq[CC * CC], sbq[CC];
    int t = threadIdx.x;
    if (t < CC * CC) sWq[t] = Wq[t];
    if (t < CC)      sbq[t] = bq[t];
    __syncthreads();

    int n = blockIdx.x * THREADS + t;
    if (n >= NQ) return;

    int b = idx_b[n];
    int s = idx_h[n] * WID + idx_w[n];

    float xv[CC];
#pragma unroll
    for (int c = 0; c < CC; c++) xv[c] = x[(b * CC + c) * HW + s];

    const float L2E = 1.4426950408889634f;
    float m = 0.0f;
#pragma unroll
    for (int o = 0; o < CC; o++) {
        float q = sbq[o];
#pragma unroll
        for (int c = 0; c < CC; c++) q = fmaf(sWq[o * CC + c], xv[c], q);
        g_qs[n * CC + o] = q * L2E;
        m = fmaf(fabsf(q), __uint_as_float(g_amax[b * CC + o]), m);
    }
    // round(tt) <= ceil(mb) for all s; bias maps r-bits -> (n - mbi)
    int mbi = (int)ceilf(m * L2E);
    g_bias[n] = -(0x4B400000 + mbi);

    int pos = atomicAdd(&g_count[b], 1);
    g_perm[b * NQ + pos] = n;
}

// ---------------------------------------------------------------------------
// Main attention kernel, fully packed f32x2: 8 queries x 16384 s-positions
// per CTA. exp2 via magic-round + deg-4 poly; max-bound folded into integer
// exponent add with IMNMX clamp (ALU pipe). Deterministic tree reduction.
__global__ void __launch_bounds__(THREADS)
attn_kernel() {
    int b   = blockIdx.y;
    int cnt = g_count[b];
    int q0  = blockIdx.x * QT;
    if (q0 >= cnt) return;
    int st  = blockIdx.z;
    int t   = threadIdx.x;
    int nq  = min(QT, cnt - q0);

    u64 qq[QT][CC];
    int bias[QT];
#pragma unroll
    for (int j = 0; j < QT; j++) {
        int slot = (j < nq) ? (q0 + j) : q0;          // pad with first query
        int n = g_perm[b * NQ + slot];
#pragma unroll
        for (int c = 0; c < CC; c++) {
            float q = g_qs[n * CC + c];
            qq[j][c] = pk2(q, q);
        }
        bias[j] = g_bias[n];
    }

    const u64* __restrict__ K2 = (const u64*)(g_K + b * CC * HW);
    const u64* __restrict__ V2 = (const u64*)(g_V + b * CC * HW);

    u64 l2[QT];
    u64 ac[QT][CC];
#pragma unroll
    for (int j = 0; j < QT; j++) {
        l2[j] = 0ull;
#pragma unroll
        for (int c = 0; c < CC; c++) ac[j][c] = 0ull;
    }

    const float MAGICF = 12582912.0f;   // 1.5 * 2^23, bits 0x4B400000
    const u64 MM   = pk2(MAGICF, MAGICF);
    const u64 NM   = pk2(-MAGICF, -MAGICF);
    const u64 NEG1 = pk2(-1.0f, -1.0f);
    const u64 C4   = pk2(0.0096181291f, 0.0096181291f);
    const u64 C3   = pk2(0.0555041087f, 0.0555041087f);
    const u64 C2   = pk2(0.2402265070f, 0.2402265070f);
    const u64 C1   = pk2(0.6931471806f, 0.6931471806f);
    const u64 ONE2 = pk2(1.0f, 1.0f);

    int sp = st * (SPER / 2) + t;

#pragma unroll 1
    for (int it = 0; it < ITERS2; it++, sp += THREADS) {
        u64 k0 = K2[sp];
        u64 k1 = K2[(HW / 2) + sp];
        u64 k2 = K2[2 * (HW / 2) + sp];
        u64 k3 = K2[3 * (HW / 2) + sp];
        u64 k4 = K2[4 * (HW / 2) + sp];
        u64 v0 = V2[sp];
        u64 v1 = V2[(HW / 2) + sp];
        u64 v2 = V2[2 * (HW / 2) + sp];
        u64 v3 = V2[3 * (HW / 2) + sp];
        u64 v4 = V2[4 * (HW / 2) + sp];

#pragma unroll
        for (int j = 0; j < QT; j++) {
            // energy * log2(e), both lanes packed
            u64 tt = mul2(qq[j][0], k0);
            tt = fma2(qq[j][1], k1, tt);
            tt = fma2(qq[j][2], k2, tt);
            tt = fma2(qq[j][3], k3, tt);
            tt = fma2(qq[j][4], k4, tt);

            // exp2: magic round + deg-4 poly on f in [-0.5, 0.5]
            u64 r  = add2(tt, MM);
            u64 rm = add2(r, NM);                 // exact: round(tt)
            u64 f  = fma2(rm, NEG1, tt);          // tt - round(tt)
            u64 p  = fma2(C4, f, C3);
            p = fma2(p, f, C2);
            p = fma2(p, f, C1);
            p = fma2(p, f, ONE2);

            // integer exponent insert with per-query bias and underflow clamp
            unsigned rlo, rhi, plo, phi;
            unpk2u(r, rlo, rhi);
            unpk2u(p, plo, phi);
            int elo = (int)rlo + bias[j];         // round(tt) - mbi
            int ehi = (int)rhi + bias[j];
            elo = max(elo, -126);                 // IMNMX, ALU pipe
            ehi = max(ehi, -126);
            plo += ((unsigned)elo << 23);
            phi += ((unsigned)ehi << 23);
            u64 pp = pk2u(plo, phi);

            l2[j] = add2(l2[j], pp);
            ac[j][0] = fma2(pp, v0, ac[j][0]);
            ac[j][1] = fma2(pp, v1, ac[j][1]);
            ac[j][2] = fma2(pp, v2, ac[j][2]);
            ac[j][3] = fma2(pp, v3, ac[j][3]);
            ac[j][4] = fma2(pp, v4, ac[j][4]);
        }
    }

    // Deterministic reduction: combine lanes -> warp butterfly -> smem -> sum
    __shared__ float red[8][QT][6];
    int warp = t >> 5, lane = t & 31;
#pragma unroll
    for (int j = 0; j < QT; j++) {
        float vals[6];
        float lo, hi;
        unpk2f(l2[j], lo, hi);
        vals[0] = lo + hi;
#pragma unroll
        for (int c = 0; c < CC; c++) {
            unpk2f(ac[j][c], lo, hi);
            vals[1 + c] = lo + hi;
        }
#pragma unroll
        for (int k = 0; k < 6; k++) {
            float v = vals[k];
#pragma unroll
            for (int off = 16; off > 0; off >>= 1)
                v += __shfl_xor_sync(0xffffffffu, v, off);
            if (lane == 0) red[warp][j][k] = v;
        }
    }
    __syncthreads();

    if (t < QT * 6) {
        int j = t / 6, k = t % 6;
        if (j < nq) {
            float ssum = 0.0f;
#pragma unroll
            for (int w2 = 0; w2 < 8; w2++) ssum += red[w2][j][k];
            int n = g_perm[b * NQ + q0 + j];
            g_part[(n * STILES + st) * 6 + k] = ssum;
        }
    }
}

// ---------------------------------------------------------------------------
__global__ void finalize_kernel(const float* __restrict__ x,
                                const float* __restrict__ gamma,
                                const int* __restrict__ idx_b, const int* __restrict__ idx_h,
                                const int* __restrict__ idx_w,
                                float* __restrict__ y) {
    int n = blockIdx.x * THREADS + threadIdx.x;
    if (n >= NQ) return;

    float l = 0.0f, a[CC] = {0.f, 0.f, 0.f, 0.f, 0.f};
#pragma unroll
    for (int st = 0; st < STILES; st++) {
        const float* p = g_part + (n * STILES + st) * 6;
        l += p[0];
#pragma unroll
        for (int c = 0; c < CC; c++) a[c] += p[1 + c];
    }

    float g = gamma[0] + 0.1f;
    float inv = 1.0f / l;
    int b = idx_b[n];
    int s = idx_h[n] * WID + idx_w[n];
#pragma unroll
    for (int c = 0; c < CC; c++) {
        float out = a[c] * inv;
        y[(b * CC + c) * HW + s] = fmaf(g, out, x[(b * CC + c) * HW + s]);
    }
}

// ---------------------------------------------------------------------------
extern "C" void kernel_launch(void* const* d_in, const int* in_sizes, int n_in,
                              void* d_out, int out_size) {
    const float* x     = (const float*)d_in[0];
    const float* Wq    = (const float*)d_in[1];
    const float* bq    = (const float*)d_in[2];
    const float* Wk    = (const float*)d_in[3];
    const float* bk    = (const float*)d_in[4];
    const float* Wv    = (const float*)d_in[5];
    const float* bv    = (const float*)d_in[6];
    const float* gamma = (const float*)d_in[7];
    const int* idx_b   = (const int*)d_in[8];
    const int* idx_h   = (const int*)d_in[9];
    const int* idx_w   = (const int*)d_in[10];
    float* y = (float*)d_out;

    init_kernel<<<1, 32>>>();
    kv_kernel<<<(BB * HW) / THREADS, THREADS>>>(x, Wk, bk, Wv, bv, y);
    qprep_kernel<<<NQ / THREADS, THREADS>>>(x, Wq, bq, idx_b, idx_h, idx_w);
    attn_kernel<<<dim3(QTILES, BB, STILES), THREADS>>>();
    finalize_kernel<<<NQ / THREADS, THREADS>>>(x, gamma, idx_b, idx_h, idx_w, y);
}

// round 4
// speedup vs baseline: 1.3233x; 1.2192x over previous
#include <cuda_runtime.h>
#include <cuda_fp16.h>
#include <cuda_bf16.h>

// Problem constants (B, C, H, W, N) = (4, 5, 256, 256, 2048)
#define BB      4
#define CC      5
#define HGT     256
#define WID     256
#define HW      65536
#define NQ      2048
#define QT      8                    // queries per CTA
#define QTILES  (NQ / QT)            // 256 (worst case all queries in one batch)
#define STILES  4                    // HW splits
#define SPER    (HW / STILES)        // 16384
#define THREADS 256
#define ITERS2  (SPER / (2 * THREADS))  // 32 half2 iters per thread

typedef __half2 h2;
typedef __nv_bfloat162 b2;

// Scratch (static device globals; no allocation allowed)
__device__ unsigned short g_Kh[BB * CC * HW];   // K as fp16
__device__ unsigned short g_Vb[BB * CC * HW];   // V as bf16
__device__ unsigned short g_qh[NQ * CC];        // q_pix * log2(e), fp16 bits
__device__ unsigned short g_thr[NQ];            // clamp threshold (mbi-120), fp16 bits
__device__ int      g_bw[NQ];                   // (112 - mbi - 0x6600) << 7
__device__ int      g_count[BB];
__device__ int      g_perm[BB * NQ];
__device__ unsigned g_amax[BB * CC];            // max |K| per (b,c), float bits
__device__ float    g_part[NQ * STILES * 6];    // per (query, s-tile): [l, acc0..acc4]

__device__ __forceinline__ h2 u2h2(unsigned u) { h2 r; *(unsigned*)&r = u; return r; }
__device__ __forceinline__ b2 u2b2(unsigned u) { b2 r; *(unsigned*)&r = u; return r; }
__device__ __forceinline__ unsigned h22u(h2 v) { return *(unsigned*)&v; }

// ---------------------------------------------------------------------------
__global__ void init_kernel() {
    int t = threadIdx.x;
    if (t < BB) g_count[t] = 0;
    if (t < BB * CC) g_amax[t] = 0u;
}

// ---------------------------------------------------------------------------
// K,V 1x1 conv (fp32 math, store K fp16 / V bf16) + y = x copy + max|K| reduce
__global__ void kv_kernel(const float* __restrict__ x,
                          const float* __restrict__ Wk, const float* __restrict__ bk,
                          const float* __restrict__ Wv, const float* __restrict__ bv,
                          float* __restrict__ y) {
    __shared__ float sWk[CC * CC], sWv[CC * CC], sbk[CC], sbv[CC];
    __shared__ unsigned samax[CC];
    int t = threadIdx.x;
    if (t < CC * CC) { sWk[t] = Wk[t]; sWv[t] = Wv[t]; }
    if (t < CC)      { sbk[t] = bk[t]; sbv[t] = bv[t]; samax[t] = 0u; }
    __syncthreads();

    int idx = blockIdx.x * THREADS + t;   // b uniform per block
    int b = idx >> 16;
    int s = idx & (HW - 1);

    float xv[CC];
#pragma unroll
    for (int c = 0; c < CC; c++) {
        xv[c] = x[(b * CC + c) * HW + s];
        y[(b * CC + c) * HW + s] = xv[c];   // residual base copy
    }

    float ka[CC];
#pragma unroll
    for (int o = 0; o < CC; o++) {
        float kk = sbk[o], vv = sbv[o];
#pragma unroll
        for (int c = 0; c < CC; c++) {
            kk = fmaf(sWk[o * CC + c], xv[c], kk);
            vv = fmaf(sWv[o * CC + c], xv[c], vv);
        }
        g_Kh[(b * CC + o) * HW + s] = __half_as_ushort(__float2half_rn(kk));
        g_Vb[(b * CC + o) * HW + s] = __bfloat16_as_ushort(__float2bfloat16_rn(vv));
        ka[o] = fabsf(kk);
    }

    int lane = t & 31;
#pragma unroll
    for (int o = 0; o < CC; o++) {
        float m = ka[o];
#pragma unroll
        for (int off = 16; off > 0; off >>= 1)
            m = fmaxf(m, __shfl_xor_sync(0xffffffffu, m, off));
        if (lane == 0) atomicMax(&samax[o], __float_as_uint(m));
    }
    __syncthreads();
    if (t < CC) atomicMax(&g_amax[b * CC + t], samax[t]);
}

// ---------------------------------------------------------------------------
// q_pix (fp16), exponent-bias constants, clamp threshold, batch bucketing
__global__ void qprep_kernel(const float* __restrict__ x,
                             const float* __restrict__ Wq, const float* __restrict__ bq,
                             const int* __restrict__ idx_b, const int* __restrict__ idx_h,
                             const int* __restrict__ idx_w) {
    __shared__ float sWq[CC * CC], sbq[CC];
    int t = threadIdx.x;
    if (t < CC * CC) sWq[t] = Wq[t];
    if (t < CC)      sbq[t] = bq[t];
    __syncthreads();

    int n = blockIdx.x * THREADS + t;
    if (n >= NQ) return;

    int b = idx_b[n];
    int s = idx_h[n] * WID + idx_w[n];

    float xv[CC];
#pragma unroll
    for (int c = 0; c < CC; c++) xv[c] = x[(b * CC + c) * HW + s];

    const float L2E = 1.4426950408889634f;
    float m = 0.0f;
#pragma unroll
    for (int o = 0; o < CC; o++) {
        float q = sbq[o];
#pragma unroll
        for (int c = 0; c < CC; c++) q = fmaf(sWq[o * CC + c], xv[c], q);
        g_qh[n * CC + o] = __half_as_ushort(__float2half_rn(q * L2E));
        m = fmaf(fabsf(q), __uint_as_float(g_amax[b * CC + o]), m);
    }
    // mbi >= round(t) for all s (fp16 margin +1)
    int mbi = (int)ceilf(m * L2E) + 1;
    g_bw[n]  = (112 - mbi - 0x6600) << 7;   // folds bf16 exp bias, -mbi, magic bits
    g_thr[n] = __half_as_ushort(__float2half_rn((float)(mbi - 120)));

    int pos = atomicAdd(&g_count[b], 1);
    g_perm[b * NQ + pos] = n;
}

// ---------------------------------------------------------------------------
// Main attention: fp16x2 energy/exp2 (full-rate HFMA2), ALU-pipe weight build
// into bf16 (wide exponent, no underflow), bf16x2 full-rate accumulation.
// K/V prefetched one iteration ahead. Deterministic fp32 tree reduction.
__global__ void __launch_bounds__(THREADS)
attn_kernel() {
    int b   = blockIdx.y;
    int cnt = g_count[b];
    int q0  = blockIdx.x * QT;
    if (q0 >= cnt) return;
    int st  = blockIdx.z;
    int t   = threadIdx.x;
    int nq  = min(QT, cnt - q0);

    h2  qh[QT][CC];
    h2  thr[QT];
    int bw[QT];
#pragma unroll
    for (int j = 0; j < QT; j++) {
        int slot = (j < nq) ? (q0 + j) : q0;          // pad with first query
        int n = g_perm[b * NQ + slot];
#pragma unroll
        for (int c = 0; c < CC; c++)
            qh[j][c] = __half2half2(__ushort_as_half(g_qh[n * CC + c]));
        thr[j] = __half2half2(__ushort_as_half(g_thr[n]));
        bw[j]  = g_bw[n];
    }

    const unsigned* __restrict__ Kh = (const unsigned*)(g_Kh + (size_t)b * CC * HW);
    const unsigned* __restrict__ Vb = (const unsigned*)(g_Vb + (size_t)b * CC * HW);

    b2 l2[QT];
    b2 ac[QT][CC];
    b2 zb = __float2bfloat162_rn(0.0f);
#pragma unroll
    for (int j = 0; j < QT; j++) {
        l2[j] = zb;
#pragma unroll
        for (int c = 0; c < CC; c++) ac[j][c] = zb;
    }

    const h2 MAG = __float2half2_rn(1536.0f);         // 1.5 * 2^10
    const h2 C3  = __float2half2_rn(0.0555041f);
    const h2 C2  = __float2half2_rn(0.2426320f);      // Taylor + f^4 economization
    const h2 C1  = __float2half2_rn(0.6931472f);
    const h2 C0  = __float2half2_rn(0.9999250f);

    int sp = st * (SPER / 2) + t;
    unsigned kc[CC], vc[CC];
#pragma unroll
    for (int c = 0; c < CC; c++) {
        kc[c] = Kh[c * (HW / 2) + sp];
        vc[c] = Vb[c * (HW / 2) + sp];
    }

#pragma unroll 1
    for (int it = 0; it < ITERS2; it++) {
        int spn = (it == ITERS2 - 1) ? sp : sp + THREADS;
        unsigned kn[CC], vn[CC];
#pragma unroll
        for (int c = 0; c < CC; c++) {
            kn[c] = Kh[c * (HW / 2) + spn];
            vn[c] = Vb[c * (HW / 2) + spn];
        }

        h2 K0 = u2h2(kc[0]), K1 = u2h2(kc[1]), K2 = u2h2(kc[2]);
        h2 K3 = u2h2(kc[3]), K4 = u2h2(kc[4]);
        b2 V0 = u2b2(vc[0]), V1 = u2b2(vc[1]), V2 = u2b2(vc[2]);
        b2 V3 = u2b2(vc[3]), V4 = u2b2(vc[4]);

#pragma unroll
        for (int j = 0; j < QT; j++) {
            // energy * log2(e) in fp16x2 (2 s-positions)
            h2 tt = __hmul2(qh[j][0], K0);
            tt = __hfma2(qh[j][1], K1, tt);
            tt = __hfma2(qh[j][2], K2, tt);
            tt = __hfma2(qh[j][3], K3, tt);
            tt = __hfma2(qh[j][4], K4, tt);
            tt = __hmax2(tt, thr[j]);                 // underflow guard

            // exp2 split: n = round(tt) via magic, f in [-0.5, 0.5]
            h2 r  = __hadd2(tt, MAG);                 // integer-rounded, ulp=1
            h2 nh = __hsub2(r, MAG);
            h2 f  = __hsub2(tt, nh);
            h2 p  = __hfma2(C3, f, C2);
            p = __hfma2(p, f, C1);
            p = __hfma2(p, f, C0);

            // Build bf16 weights on ALU pipe:
            // w = (p_h>>3) + ((r_bits - 0x6600 + 112 - mbi) << 7)  per lane
            unsigned R = h22u(r), P = h22u(p);
            unsigned w0 = ((P & 0xFFFFu) >> 3) + ((R & 0xFFFFu) << 7) + (unsigned)bw[j];
            unsigned w1 = (P >> 19) + ((R >> 9) & 0x007FFF80u) + (unsigned)bw[j];
            b2 w2 = u2b2(__byte_perm(w0, w1, 0x5410));

            l2[j]    = __hadd2(l2[j], w2);
            ac[j][0] = __hfma2(w2, V0, ac[j][0]);
            ac[j][1] = __hfma2(w2, V1, ac[j][1]);
            ac[j][2] = __hfma2(w2, V2, ac[j][2]);
            ac[j][3] = __hfma2(w2, V3, ac[j][3]);
            ac[j][4] = __hfma2(w2, V4, ac[j][4]);
        }

#pragma unroll
        for (int c = 0; c < CC; c++) { kc[c] = kn[c]; vc[c] = vn[c]; }
        sp = spn;
    }

    // Deterministic reduction: lanes -> fp32, warp butterfly -> smem -> sum
    __shared__ float red[8][QT][6];
    int warp = t >> 5, lane = t & 31;
#pragma unroll
    for (int j = 0; j < QT; j++) {
        float vals[6];
        vals[0] = __low2float(l2[j]) + __high2float(l2[j]);
#pragma unroll
        for (int c = 0; c < CC; c++)
            vals[1 + c] = __low2float(ac[j][c]) + __high2float(ac[j][c]);
#pragma unroll
        for (int k = 0; k < 6; k++) {
            float v = vals[k];
#pragma unroll
            for (int off = 16; off > 0; off >>= 1)
                v += __shfl_xor_sync(0xffffffffu, v, off);
            if (lane == 0) red[warp][j][k] = v;
        }
    }
    __syncthreads();

    if (t < QT * 6) {
        int j = t / 6, k = t % 6;
        if (j < nq) {
            float ssum = 0.0f;
#pragma unroll
            for (int w2i = 0; w2i < 8; w2i++) ssum += red[w2i][j][k];
            int n = g_perm[b * NQ + q0 + j];
            g_part[(n * STILES + st) * 6 + k] = ssum;
        }
    }
}

// ---------------------------------------------------------------------------
__global__ void finalize_kernel(const float* __restrict__ x,
                                const float* __restrict__ gamma,
                                const int* __restrict__ idx_b, const int* __restrict__ idx_h,
                                const int* __restrict__ idx_w,
                                float* __restrict__ y) {
    int n = blockIdx.x * THREADS + threadIdx.x;
    if (n >= NQ) return;

    float l = 0.0f, a[CC] = {0.f, 0.f, 0.f, 0.f, 0.f};
#pragma unroll
    for (int st = 0; st < STILES; st++) {
        const float* p = g_part + (n * STILES + st) * 6;
        l += p[0];
#pragma unroll
        for (int c = 0; c < CC; c++) a[c] += p[1 + c];
    }

    float g = gamma[0] + 0.1f;
    float inv = 1.0f / l;
    int b = idx_b[n];
    int s = idx_h[n] * WID + idx_w[n];
#pragma unroll
    for (int c = 0; c < CC; c++) {
        float out = a[c] * inv;
        y[(b * CC + c) * HW + s] = fmaf(g, out, x[(b * CC + c) * HW + s]);
    }
}

// ---------------------------------------------------------------------------
extern "C" void kernel_launch(void* const* d_in, const int* in_sizes, int n_in,
                              void* d_out, int out_size) {
    const float* x     = (const float*)d_in[0];
    const float* Wq    = (const float*)d_in[1];
    const float* bq    = (const float*)d_in[2];
    const float* Wk    = (const float*)d_in[3];
    const float* bk    = (const float*)d_in[4];
    const float* Wv    = (const float*)d_in[5];
    const float* bv    = (const float*)d_in[6];
    const float* gamma = (const float*)d_in[7];
    const int* idx_b   = (const int*)d_in[8];
    const int* idx_h   = (const int*)d_in[9];
    const int* idx_w   = (const int*)d_in[10];
    float* y = (float*)d_out;

    init_kernel<<<1, 32>>>();
    kv_kernel<<<(BB * HW) / THREADS, THREADS>>>(x, Wk, bk, Wv, bv, y);
    qprep_kernel<<<NQ / THREADS, THREADS>>>(x, Wq, bq, idx_b, idx_h, idx_w);
    attn_kernel<<<dim3(QTILES, BB, STILES), THREADS>>>();
    finalize_kernel<<<NQ / THREADS, THREADS>>>(x, gamma, idx_b, idx_h, idx_w, y);
}

// round 5
// speedup vs baseline: 1.4666x; 1.1083x over previous
#include <cuda_runtime.h>
#include <cuda_fp16.h>
#include <cuda_bf16.h>

// Problem constants (B, C, H, W, N) = (4, 5, 256, 256, 2048)
#define BB      4
#define CC      5
#define HGT     256
#define WID     256
#define HW      65536
#define NQ      2048
#define QT      6                    // queries per CTA
#define QTILES  ((NQ + QT - 1) / QT) // 342 (worst case all queries in one batch)
#define STILES  4                    // HW splits
#define SPER    (HW / STILES)        // 16384
#define THREADS 256
#define ITERS2  (SPER / (2 * THREADS))  // 32 half2 iters per thread

typedef __half2 h2;
typedef __nv_bfloat162 b2;

// Scratch (static device globals; no allocation allowed)
__device__ unsigned short g_Kh[BB * CC * HW];   // K as fp16
__device__ unsigned short g_Vb[BB * CC * HW];   // V as bf16
__device__ unsigned short g_qh[NQ * CC];        // q_pix * log2(e), fp16 bits
__device__ int      g_bw[NQ];                   // (112 - mbi - 0x6600) << 7
__device__ int      g_count[BB];
__device__ int      g_perm[BB * NQ];
__device__ unsigned g_amax[BB * CC];            // max |K| per (b,c), float bits
__device__ float    g_part[NQ * STILES * 6];    // per (query, s-tile): [l, acc0..acc4]

__device__ __forceinline__ h2 u2h2(unsigned u) { h2 r; *(unsigned*)&r = u; return r; }
__device__ __forceinline__ b2 u2b2(unsigned u) { b2 r; *(unsigned*)&r = u; return r; }
__device__ __forceinline__ unsigned h22u(h2 v) { return *(unsigned*)&v; }

// ---------------------------------------------------------------------------
__global__ void init_kernel() {
    int t = threadIdx.x;
    if (t < BB) g_count[t] = 0;
    if (t < BB * CC) g_amax[t] = 0u;
}

// ---------------------------------------------------------------------------
// K,V 1x1 conv (fp32 math, store K fp16 / V bf16) + y = x copy + max|K| reduce
__global__ void kv_kernel(const float* __restrict__ x,
                          const float* __restrict__ Wk, const float* __restrict__ bk,
                          const float* __restrict__ Wv, const float* __restrict__ bv,
                          float* __restrict__ y) {
    __shared__ float sWk[CC * CC], sWv[CC * CC], sbk[CC], sbv[CC];
    __shared__ unsigned samax[CC];
    int t = threadIdx.x;
    if (t < CC * CC) { sWk[t] = Wk[t]; sWv[t] = Wv[t]; }
    if (t < CC)      { sbk[t] = bk[t]; sbv[t] = bv[t]; samax[t] = 0u; }
    __syncthreads();

    int idx = blockIdx.x * THREADS + t;   // b uniform per block
    int b = idx >> 16;
    int s = idx & (HW - 1);

    float xv[CC];
#pragma unroll
    for (int c = 0; c < CC; c++) {
        xv[c] = x[(b * CC + c) * HW + s];
        y[(b * CC + c) * HW + s] = xv[c];   // residual base copy
    }

    float ka[CC];
#pragma unroll
    for (int o = 0; o < CC; o++) {
        float kk = sbk[o], vv = sbv[o];
#pragma unroll
        for (int c = 0; c < CC; c++) {
            kk = fmaf(sWk[o * CC + c], xv[c], kk);
            vv = fmaf(sWv[o * CC + c], xv[c], vv);
        }
        g_Kh[(b * CC + o) * HW + s] = __half_as_ushort(__float2half_rn(kk));
        g_Vb[(b * CC + o) * HW + s] = __bfloat16_as_ushort(__float2bfloat16_rn(vv));
        ka[o] = fabsf(kk);
    }

    int lane = t & 31;
#pragma unroll
    for (int o = 0; o < CC; o++) {
        float m = ka[o];
#pragma unroll
        for (int off = 16; off > 0; off >>= 1)
            m = fmaxf(m, __shfl_xor_sync(0xffffffffu, m, off));
        if (lane == 0) atomicMax(&samax[o], __float_as_uint(m));
    }
    __syncthreads();
    if (t < CC) atomicMax(&g_amax[b * CC + t], samax[t]);
}

// ---------------------------------------------------------------------------
// q_pix (fp16), exponent-bias constant, batch bucketing
__global__ void qprep_kernel(const float* __restrict__ x,
                             const float* __restrict__ Wq, const float* __restrict__ bq,
                             const int* __restrict__ idx_b, const int* __restrict__ idx_h,
                             const int* __restrict__ idx_w) {
    __shared__ float sWq[CC * CC], sbq[CC];
    int t = threadIdx.x;
    if (t < CC * CC) sWq[t] = Wq[t];
    if (t < CC)      sbq[t] = bq[t];
    __syncthreads();

    int n = blockIdx.x * THREADS + t;
    if (n >= NQ) return;

    int b = idx_b[n];
    int s = idx_h[n] * WID + idx_w[n];

    float xv[CC];
#pragma unroll
    for (int c = 0; c < CC; c++) xv[c] = x[(b * CC + c) * HW + s];

    const float L2E = 1.4426950408889634f;
    float m = 0.0f;
#pragma unroll
    for (int o = 0; o < CC; o++) {
        float q = sbq[o];
#pragma unroll
        for (int c = 0; c < CC; c++) q = fmaf(sWq[o * CC + c], xv[c], q);
        g_qh[n * CC + o] = __half_as_ushort(__float2half_rn(q * L2E));
        m = fmaf(fabsf(q), __uint_as_float(g_amax[b * CC + o]), m);
    }
    // mbi >= round(t) for all s (fp16 margin +1)
    int mbi = (int)ceilf(m * L2E) + 1;
    g_bw[n] = (112 - mbi - 0x6600) << 7;   // folds bf16 exp bias, -mbi, magic bits

    int pos = atomicAdd(&g_count[b], 1);
    g_perm[b * NQ + pos] = n;
}

// ---------------------------------------------------------------------------
// Main attention: fp16x2 energy + deg-2 exp2 poly (full-rate HFMA2), ALU-pipe
// weight build into bf16 with integer underflow clamp (IMNMX), bf16x2
// full-rate accumulation. 2 CTAs/SM (128-reg cap) for latency hiding.
__global__ void __launch_bounds__(THREADS, 2)
attn_kernel() {
    int b   = blockIdx.y;
    int cnt = g_count[b];
    int q0  = blockIdx.x * QT;
    if (q0 >= cnt) return;
    int st  = blockIdx.z;
    int t   = threadIdx.x;
    int nq  = min(QT, cnt - q0);

    h2  qh[QT][CC];
    int bw[QT];
#pragma unroll
    for (int j = 0; j < QT; j++) {
        int slot = (j < nq) ? (q0 + j) : q0;          // pad with first query
        int n = g_perm[b * NQ + slot];
#pragma unroll
        for (int c = 0; c < CC; c++)
            qh[j][c] = __half2half2(__ushort_as_half(g_qh[n * CC + c]));
        bw[j] = g_bw[n];
    }

    const unsigned* __restrict__ Kh = (const unsigned*)(g_Kh + (size_t)b * CC * HW);
    const unsigned* __restrict__ Vb = (const unsigned*)(g_Vb + (size_t)b * CC * HW);

    b2 l2[QT];
    b2 ac[QT][CC];
    b2 zb = __float2bfloat162_rn(0.0f);
#pragma unroll
    for (int j = 0; j < QT; j++) {
        l2[j] = zb;
#pragma unroll
        for (int c = 0; c < CC; c++) ac[j][c] = zb;
    }

    const h2 MAG = __float2half2_rn(1536.0f);         // 1.5 * 2^10
    const h2 C2  = __float2half2_rn(0.2428f);         // deg-2 minimax 2^f
    const h2 C1  = __float2half2_rn(0.7021f);
    const h2 C0  = __float2half2_rn(0.9999f);

    int sp = st * (SPER / 2) + t;

#pragma unroll 1
    for (int it = 0; it < ITERS2; it++, sp += THREADS) {
        h2 K0 = u2h2(Kh[0 * (HW / 2) + sp]);
        h2 K1 = u2h2(Kh[1 * (HW / 2) + sp]);
        h2 K2 = u2h2(Kh[2 * (HW / 2) + sp]);
        h2 K3 = u2h2(Kh[3 * (HW / 2) + sp]);
        h2 K4 = u2h2(Kh[4 * (HW / 2) + sp]);
        b2 V0 = u2b2(Vb[0 * (HW / 2) + sp]);
        b2 V1 = u2b2(Vb[1 * (HW / 2) + sp]);
        b2 V2 = u2b2(Vb[2 * (HW / 2) + sp]);
        b2 V3 = u2b2(Vb[3 * (HW / 2) + sp]);
        b2 V4 = u2b2(Vb[4 * (HW / 2) + sp]);

#pragma unroll
        for (int j = 0; j < QT; j++) {
            // energy * log2(e) in fp16x2 (2 s-positions)
            h2 tt = __hmul2(qh[j][0], K0);
            tt = __hfma2(qh[j][1], K1, tt);
            tt = __hfma2(qh[j][2], K2, tt);
            tt = __hfma2(qh[j][3], K3, tt);
            tt = __hfma2(qh[j][4], K4, tt);

            // exp2 split: n = round(tt) via magic, f in [-0.5, 0.5]
            h2 r  = __hadd2(tt, MAG);                 // integer-rounded, ulp=1
            h2 nh = __hsub2(r, MAG);
            h2 f  = __hsub2(tt, nh);
            h2 p  = __hfma2(C2, f, C1);
            p = __hfma2(p, f, C0);

            // Build bf16 weights on ALU pipe:
            // w = (p_h>>3) + ((r_bits - 0x6600 + 112 - mbi) << 7) per lane,
            // signed clamp at 0 handles underflow (replaces hmax2)
            unsigned R = h22u(r), P = h22u(p);
            int w0 = (int)(((P & 0xFFFFu) >> 3) + ((R & 0xFFFFu) << 7)) + bw[j];
            int w1 = (int)((P >> 19) + ((R >> 9) & 0x007FFF80u)) + bw[j];
            w0 = max(w0, 0);                          // IMNMX, ALU pipe
            w1 = max(w1, 0);
            b2 w2 = u2b2(__byte_perm((unsigned)w0, (unsigned)w1, 0x5410));

            l2[j]    = __hadd2(l2[j], w2);
            ac[j][0] = __hfma2(w2, V0, ac[j][0]);
            ac[j][1] = __hfma2(w2, V1, ac[j][1]);
            ac[j][2] = __hfma2(w2, V2, ac[j][2]);
            ac[j][3] = __hfma2(w2, V3, ac[j][3]);
            ac[j][4] = __hfma2(w2, V4, ac[j][4]);
        }
    }

    // Deterministic reduction: lanes -> fp32, warp butterfly -> smem -> sum
    __shared__ float red[8][QT][6];
    int warp = t >> 5, lane = t & 31;
#pragma unroll
    for (int j = 0; j < QT; j++) {
        float vals[6];
        vals[0] = __low2float(l2[j]) + __high2float(l2[j]);
#pragma unroll
        for (int c = 0; c < CC; c++)
            vals[1 + c] = __low2float(ac[j][c]) + __high2float(ac[j][c]);
#pragma unroll
        for (int k = 0; k < 6; k++) {
            float v = vals[k];
#pragma unroll
            for (int off = 16; off > 0; off >>= 1)
                v += __shfl_xor_sync(0xffffffffu, v, off);
            if (lane == 0) red[warp][j][k] = v;
        }
    }
    __syncthreads();

    if (t < QT * 6) {
        int j = t / 6, k = t % 6;
        if (j < nq) {
            float ssum = 0.0f;
#pragma unroll
            for (int w2i = 0; w2i < 8; w2i++) ssum += red[w2i][j][k];
            int n = g_perm[b * NQ + q0 + j];
            g_part[(n * STILES + st) * 6 + k] = ssum;
        }
    }
}

// ---------------------------------------------------------------------------
__global__ void finalize_kernel(const float* __restrict__ x,
                                const float* __restrict__ gamma,
                                const int* __restrict__ idx_b, const int* __restrict__ idx_h,
                                const int* __restrict__ idx_w,
                                float* __restrict__ y) {
    int n = blockIdx.x * THREADS + threadIdx.x;
    if (n >= NQ) return;

    float l = 0.0f, a[CC] = {0.f, 0.f, 0.f, 0.f, 0.f};
#pragma unroll
    for (int st = 0; st < STILES; st++) {
        const float* p = g_part + (n * STILES + st) * 6;
        l += p[0];
#pragma unroll
        for (int c = 0; c < CC; c++) a[c] += p[1 + c];
    }

    float g = gamma[0] + 0.1f;
    float inv = 1.0f / l;
    int b = idx_b[n];
    int s = idx_h[n] * WID + idx_w[n];
#pragma unroll
    for (int c = 0; c < CC; c++) {
        float out = a[c] * inv;
        y[(b * CC + c) * HW + s] = fmaf(g, out, x[(b * CC + c) * HW + s]);
    }
}

// ---------------------------------------------------------------------------
extern "C" void kernel_launch(void* const* d_in, const int* in_sizes, int n_in,
                              void* d_out, int out_size) {
    const float* x     = (const float*)d_in[0];
    const float* Wq    = (const float*)d_in[1];
    const float* bq    = (const float*)d_in[2];
    const float* Wk    = (const float*)d_in[3];
    const float* bk    = (const float*)d_in[4];
    const float* Wv    = (const float*)d_in[5];
    const float* bv    = (const float*)d_in[6];
    const float* gamma = (const float*)d_in[7];
    const int* idx_b   = (const int*)d_in[8];
    const int* idx_h   = (const int*)d_in[9];
    const int* idx_w   = (const int*)d_in[10];
    float* y = (float*)d_out;

    init_kernel<<<1, 32>>>();
    kv_kernel<<<(BB * HW) / THREADS, THREADS>>>(x, Wk, bk, Wv, bv, y);
    qprep_kernel<<<NQ / THREADS, THREADS>>>(x, Wq, bq, idx_b, idx_h, idx_w);
    attn_kernel<<<dim3(QTILES, BB, STILES), THREADS>>>();
    finalize_kernel<<<NQ / THREADS, THREADS>>>(x, gamma, idx_b, idx_h, idx_w, y);
}